// round 2
// baseline (speedup 1.0000x reference)
#include <cuda_runtime.h>
#include <cuda_bf16.h>
#include <math.h>
#include <stdint.h>

#define Bc 128
#define Tc 32
#define Fc 2048
#define G3 6144
#define Hc 64
#define Nn 4096

// ---- static scratch (no cudaMalloc allowed) ----
__device__ float g_Xs[Bc*Tc*Fc];
__device__ float g_Gi[(size_t)Bc*Tc*G3];
__device__ float g_H0[Bc*Tc*Fc];
__device__ float g_Emb[Bc*Tc*Fc];
__device__ float g_hz[Tc*Fc];
__device__ float g_P[4*Tc*G3];
__device__ float g_XN[Nn*Hc];
__device__ float g_XL[Nn*Hc];
__device__ float g_XR[Nn*Hc];
__device__ float g_G0[Nn*Hc];
__device__ float g_G1[Nn*Hc];
__device__ float g_FUS[Nn*2*Hc];
__device__ float g_PR[(size_t)Nn*2048];

// ---- packed f32x2 helpers ----
__device__ __forceinline__ unsigned long long pk2(float x){
    unsigned long long r; asm("mov.b64 %0,{%1,%1};" : "=l"(r) : "f"(x)); return r;
}
__device__ __forceinline__ void ffma2(unsigned long long& d, unsigned long long a, unsigned long long b){
    asm("fma.rn.f32x2 %0,%1,%2,%0;" : "+l"(d) : "l"(a), "l"(b));
}
__device__ __forceinline__ float2 up2(unsigned long long v){
    float2 r; asm("mov.b64 {%0,%1},%2;" : "=f"(r.x), "=f"(r.y) : "l"(v)); return r;
}

// ---- utility ----
__global__ void k_zero(float* p, int n){ int i=blockIdx.x*256+threadIdx.x; if(i<n) p[i]=0.f; }

__global__ void k_sanitize(const float* __restrict__ in, float* __restrict__ out, int n){
    int i = blockIdx.x*256 + threadIdx.x;
    if(i<n){
        float v = in[i];
        if (isnan(v)) v = 0.f;
        else if (isinf(v)) v = (v>0.f) ? 1.0f : -3.4028234663852886e38f;
        out[i] = v;
    }
}

// ---- big SGEMM: C[M,N] = A[M,K] @ B[N,K]^T (+bias), 128x128 tile, f32x2 ----
__global__ void __launch_bounds__(256) k_sgemm(const float* __restrict__ A,
                                               const float* __restrict__ Bm,
                                               const float* __restrict__ bias,
                                               float* __restrict__ C,
                                               int Ncols, int K)
{
    __shared__ float As[8][128];
    __shared__ float Bs[8][128];
    const int tid = threadIdx.x;
    const int tx = tid & 15, ty = tid >> 4;
    const int m0 = blockIdx.y*128, n0 = blockIdx.x*128;
    const int lr = tid >> 1, lc = (tid & 1)*4;
    const float* Ap = A + (size_t)(m0+lr)*K + lc;
    const float* Bp = Bm + (size_t)(n0+lr)*K + lc;

    unsigned long long acc[8][4];
    #pragma unroll
    for(int i=0;i<8;i++)
        #pragma unroll
        for(int j=0;j<4;j++) acc[i][j]=0ULL;

    for(int k0=0;k0<K;k0+=8){
        float4 av = *(const float4*)(Ap + k0);
        float4 bv = *(const float4*)(Bp + k0);
        __syncthreads();
        As[lc+0][lr]=av.x; As[lc+1][lr]=av.y; As[lc+2][lr]=av.z; As[lc+3][lr]=av.w;
        Bs[lc+0][lr]=bv.x; Bs[lc+1][lr]=bv.y; Bs[lc+2][lr]=bv.z; Bs[lc+3][lr]=bv.w;
        __syncthreads();
        #pragma unroll
        for(int k=0;k<8;k++){
            float4 a0 = *(const float4*)&As[k][ty*8];
            float4 a1 = *(const float4*)&As[k][ty*8+4];
            ulonglong2 b01 = *(const ulonglong2*)&Bs[k][tx*8];
            ulonglong2 b23 = *(const ulonglong2*)&Bs[k][tx*8+4];
            unsigned long long aa[8];
            aa[0]=pk2(a0.x); aa[1]=pk2(a0.y); aa[2]=pk2(a0.z); aa[3]=pk2(a0.w);
            aa[4]=pk2(a1.x); aa[5]=pk2(a1.y); aa[6]=pk2(a1.z); aa[7]=pk2(a1.w);
            #pragma unroll
            for(int i=0;i<8;i++){
                ffma2(acc[i][0], aa[i], b01.x);
                ffma2(acc[i][1], aa[i], b01.y);
                ffma2(acc[i][2], aa[i], b23.x);
                ffma2(acc[i][3], aa[i], b23.y);
            }
        }
    }
    #pragma unroll
    for(int i=0;i<8;i++){
        int row = m0 + ty*8 + i;
        #pragma unroll
        for(int j=0;j<4;j++){
            float2 v = up2(acc[i][j]);
            int col = n0 + tx*8 + j*2;
            float b0 = bias ? bias[col]   : 0.f;
            float b1 = bias ? bias[col+1] : 0.f;
            C[(size_t)row*Ncols + col]   = v.x + b0;
            C[(size_t)row*Ncols + col+1] = v.y + b1;
        }
    }
}

// ---- recurrent GEMM: P[ks][32][6144] partial of H[32,2048] @ W[6144,2048]^T ----
// grid (48, 4), block 256, K-split 512 each
__global__ void __launch_bounds__(256) k_rgemm(const float* __restrict__ H,
                                               const float* __restrict__ W,
                                               float* __restrict__ P)
{
    __shared__ float As[16][32];
    __shared__ float Bs[16][128];
    const int tid = threadIdx.x;
    const int cg = tid & 15, rg = tid >> 4;   // rg 0..15 (2 rows), cg 0..15 (8 cols)
    const int n0 = blockIdx.x * 128;
    const int kbase = blockIdx.y * 512;

    unsigned long long acc[2][4];
    #pragma unroll
    for(int i=0;i<2;i++)
        #pragma unroll
        for(int j=0;j<4;j++) acc[i][j]=0ULL;

    for(int k0=0;k0<512;k0+=16){
        float4 va;
        if(tid < 128){
            int r = tid>>2, q = tid&3;
            va = *(const float4*)(H + (size_t)r*Fc + kbase + k0 + q*4);
        }
        float4 vb0, vb1;
        {
            int r0 = tid>>2, q0 = tid&3;
            vb0 = *(const float4*)(W + (size_t)(n0+r0)*Fc + kbase + k0 + q0*4);
            int idx = tid + 256;
            int r1 = idx>>2, q1 = idx&3;
            vb1 = *(const float4*)(W + (size_t)(n0+r1)*Fc + kbase + k0 + q1*4);
        }
        __syncthreads();
        if(tid < 128){
            int r = tid>>2, q = tid&3;
            As[q*4+0][r]=va.x; As[q*4+1][r]=va.y; As[q*4+2][r]=va.z; As[q*4+3][r]=va.w;
        }
        {
            int r0 = tid>>2, q0 = tid&3;
            Bs[q0*4+0][r0]=vb0.x; Bs[q0*4+1][r0]=vb0.y; Bs[q0*4+2][r0]=vb0.z; Bs[q0*4+3][r0]=vb0.w;
            int idx = tid + 256;
            int r1 = idx>>2, q1 = idx&3;
            Bs[q1*4+0][r1]=vb1.x; Bs[q1*4+1][r1]=vb1.y; Bs[q1*4+2][r1]=vb1.z; Bs[q1*4+3][r1]=vb1.w;
        }
        __syncthreads();
        #pragma unroll
        for(int k=0;k<16;k++){
            unsigned long long a0 = pk2(As[k][rg*2]);
            unsigned long long a1 = pk2(As[k][rg*2+1]);
            ulonglong2 b01 = *(const ulonglong2*)&Bs[k][cg*8];
            ulonglong2 b23 = *(const ulonglong2*)&Bs[k][cg*8+4];
            ffma2(acc[0][0], a0, b01.x); ffma2(acc[0][1], a0, b01.y);
            ffma2(acc[0][2], a0, b23.x); ffma2(acc[0][3], a0, b23.y);
            ffma2(acc[1][0], a1, b01.x); ffma2(acc[1][1], a1, b01.y);
            ffma2(acc[1][2], a1, b23.x); ffma2(acc[1][3], a1, b23.y);
        }
    }
    float* Pb = P + (size_t)blockIdx.y*Tc*G3;
    #pragma unroll
    for(int i=0;i<2;i++){
        int row = rg*2 + i;
        #pragma unroll
        for(int j=0;j<4;j++){
            float2 v = up2(acc[i][j]);
            int col = n0 + cg*8 + j*2;
            Pb[(size_t)row*G3 + col]   = v.x;
            Pb[(size_t)row*G3 + col+1] = v.y;
        }
    }
}

// ---- GRU gate fuse: combine K-split partials + input gates + biases ----
__global__ void __launch_bounds__(256) k_gate(int b,
                                              const float* __restrict__ P,
                                              const float* __restrict__ Gi,
                                              const float* __restrict__ bhh,
                                              const float* __restrict__ Hprev,
                                              float* __restrict__ Hall)
{
    int i = blockIdx.x*256 + threadIdx.x;  // 65536 = 32*2048
    int row = i >> 11, j = i & 2047;
    float gr=0.f, gz=0.f, gn=0.f;
    #pragma unroll
    for(int ks=0;ks<4;ks++){
        const float* p = P + ((size_t)ks*Tc + row)*G3;
        gr += p[j]; gz += p[2048+j]; gn += p[4096+j];
    }
    const float* gi = Gi + ((size_t)b*Tc + row)*G3;
    float r = 1.f/(1.f + expf(-(gi[j]      + gr + bhh[j])));
    float z = 1.f/(1.f + expf(-(gi[2048+j] + gz + bhh[2048+j])));
    float n = tanhf(gi[4096+j] + r*(gn + bhh[4096+j]));
    float h = Hprev[(size_t)row*Fc + j];
    Hall[((size_t)b*Tc + row)*Fc + j] = (1.f - z)*n + z*h;
}

// ---- temporal attention over T=32 per (b,f) ----
__global__ void __launch_bounds__(256) k_attn(const float* __restrict__ Emb,
                                              const float* __restrict__ Aw,
                                              const float* __restrict__ Ab,
                                              float* __restrict__ XN)
{
    __shared__ float sW[32][33];
    __shared__ float sB[32];
    int tid = threadIdx.x;
    for(int i=tid;i<1024;i+=256) sW[i>>5][i&31] = Aw[i];
    if(tid<32) sB[tid]=Ab[tid];
    __syncthreads();
    int g = blockIdx.x*256 + tid;        // b*2048 + f
    int b = g >> 11, f = g & 2047;
    float tA[32];
    #pragma unroll
    for(int t=0;t<32;t++) tA[t] = tanhf(Emb[((size_t)b*32 + t)*Fc + f]);
    float mx = -1e30f, aw[32];
    #pragma unroll
    for(int t2=0;t2<32;t2++){
        float s = sB[t2];
        #pragma unroll
        for(int t=0;t<32;t++) s += tA[t]*sW[t2][t];
        aw[t2]=s; mx = fmaxf(mx, s);
    }
    float den=0.f, num=0.f;
    #pragma unroll
    for(int t=0;t<32;t++){ float e = expf(aw[t]-mx); den += e; num += e*tA[t]; }
    XN[g] = tanhf(num/den);
}

// ---- GAT projections: XL = X@Wl^T+bl, XR = X@Wr^T+br (64x64) ----
__global__ void __launch_bounds__(256) k_lin64(const float* __restrict__ X,
                                               const float* __restrict__ Wl, const float* __restrict__ bl,
                                               const float* __restrict__ Wr, const float* __restrict__ br,
                                               float* __restrict__ XL, float* __restrict__ XR)
{
    __shared__ float sX[64][65];
    __shared__ float sW[64][65];
    int tid = threadIdx.x;
    int r0 = blockIdx.x*64;
    for(int i=tid;i<4096;i+=256){ int r=i>>6, c=i&63; sX[r][c]=X[(size_t)(r0+r)*64+c]; }
    for(int i=tid;i<4096;i+=256){ int r=i>>6, c=i&63; sW[r][c]=Wl[i]; }
    __syncthreads();
    int r = tid & 63, cq = tid >> 6;
    #pragma unroll 4
    for(int cc=0; cc<16; cc++){
        int c = cq*16 + cc;
        float s = bl[c];
        #pragma unroll
        for(int k=0;k<64;k++) s += sX[r][k]*sW[c][k];
        XL[(size_t)(r0+r)*64 + c] = s;
    }
    __syncthreads();
    for(int i=tid;i<4096;i+=256){ int rr=i>>6, c=i&63; sW[rr][c]=Wr[i]; }
    __syncthreads();
    #pragma unroll 4
    for(int cc=0; cc<16; cc++){
        int c = cq*16 + cc;
        float s = br[c];
        #pragma unroll
        for(int k=0;k<64;k++) s += sX[r][k]*sW[c][k];
        XR[(size_t)(r0+r)*64 + c] = s;
    }
}

// ---- GATv2 on dense 32x32 block graph; one warp per dst node; tanh output ----
__global__ void __launch_bounds__(128) k_gat(const float* __restrict__ XL,
                                             const float* __restrict__ XR,
                                             const float* __restrict__ att,
                                             const float* __restrict__ bias,
                                             float* __restrict__ OUT)
{
    int w = threadIdx.x >> 5, lane = threadIdx.x & 31;
    int g = blockIdx.x >> 3;
    int d = ((blockIdx.x & 7) << 2) + w;
    int nd = g*32 + d;
    float xr0 = XR[(size_t)nd*64 + lane];
    float xr1 = XR[(size_t)nd*64 + 32 + lane];
    float a0 = att[lane], a1 = att[lane+32];
    const float* xlg = XL + (size_t)g*32*64;
    float lg[32];
    #pragma unroll
    for(int s=0;s<32;s++){
        float u = xlg[s*64 + lane]      + xr0;
        float v = xlg[s*64 + 32 + lane] + xr1;
        u = u>0.f ? u : 0.2f*u;
        v = v>0.f ? v : 0.2f*v;
        float t = u*a0 + v*a1;
        #pragma unroll
        for(int o=16;o>0;o>>=1) t += __shfl_xor_sync(0xffffffffu, t, o);
        lg[s] = t;
    }
    float m = -1e30f;
    #pragma unroll
    for(int s=0;s<32;s++) m = fmaxf(m, lg[s]);
    float den = 0.f;
    #pragma unroll
    for(int s=0;s<32;s++){ lg[s] = expf(lg[s]-m); den += lg[s]; }
    float inv = 1.f/den, o0=0.f, o1=0.f;
    #pragma unroll
    for(int s=0;s<32;s++){
        float al = lg[s]*inv;
        o0 += al * xlg[s*64 + lane];
        o1 += al * xlg[s*64 + 32 + lane];
    }
    OUT[(size_t)nd*64 + lane]      = tanhf(o0 + bias[lane]);
    OUT[(size_t)nd*64 + 32 + lane] = tanhf(o1 + bias[lane+32]);
}

// ---- fusion concat ----
__global__ void k_fus(const float* __restrict__ XN, const float* __restrict__ G0,
                      const float* __restrict__ G1, float* __restrict__ FUS)
{
    int i = blockIdx.x*256 + threadIdx.x;  // 4096*128
    int n = i >> 7, q = i & 127;
    FUS[i] = (q < 64) ? XN[(size_t)n*64 + q]
                      : (G0[(size_t)n*64 + q-64] + G1[(size_t)n*64 + q-64]);
}

// ---- capsule routing (3 iters) + final head, block per batch n, thread per l ----
__global__ void __launch_bounds__(64) k_route(const float* __restrict__ PR,
                                              const float* __restrict__ Fw,
                                              const float* __restrict__ Fb,
                                              float* __restrict__ out)
{
    int n = blockIdx.x, l = threadIdx.x;
    const float* base = PR + (size_t)n*65536 + l;   // idx: c*2048 + o*64
    float o0[32], o1[32], pc[32], te[32];
    // pass 0: out0[o] = mean over c
    #pragma unroll
    for(int o=0;o<32;o++) o0[o]=0.f;
    for(int c=0;c<32;c++){
        const float* pcol = base + (size_t)c*2048;
        #pragma unroll
        for(int o=0;o<32;o++) o0[o] += pcol[o*64];
    }
    #pragma unroll
    for(int o=0;o<32;o++){ o0[o] *= (1.f/32.f); o1[o]=0.f; }
    // pass 1: out1
    for(int c=0;c<32;c++){
        const float* pcol = base + (size_t)c*2048;
        float m = -1e30f;
        #pragma unroll
        for(int o=0;o<32;o++){ pc[o]=pcol[o*64]; float lgv = pc[o]*o0[o]; te[o]=lgv; m = fmaxf(m,lgv); }
        float den=0.f;
        #pragma unroll
        for(int o=0;o<32;o++){ te[o]=expf(te[o]-m); den+=te[o]; }
        float inv = 1.f/den;
        #pragma unroll
        for(int o=0;o<32;o++) o1[o] += te[o]*inv*pc[o];
    }
    // pass 2: factor = out0+out1, out2 accumulated into o1
    #pragma unroll
    for(int o=0;o<32;o++){ o0[o] += o1[o]; o1[o]=0.f; }
    for(int c=0;c<32;c++){
        const float* pcol = base + (size_t)c*2048;
        float m = -1e30f;
        #pragma unroll
        for(int o=0;o<32;o++){ pc[o]=pcol[o*64]; float lgv = pc[o]*o0[o]; te[o]=lgv; m = fmaxf(m,lgv); }
        float den=0.f;
        #pragma unroll
        for(int o=0;o<32;o++){ te[o]=expf(te[o]-m); den+=te[o]; }
        float inv = 1.f/den;
        #pragma unroll
        for(int o=0;o<32;o++) o1[o] += te[o]*inv*pc[o];
    }
    __shared__ float sc[32][65];
    #pragma unroll
    for(int o=0;o<32;o++) sc[o][l] = tanhf(o1[o]);
    __syncthreads();
    // final: out[n,o,d2] = tanh( sum_l sc[o][l]*Fw[d2,l] + Fb[d2] ), 1024 outputs / 64 thr
    for(int q=0;q<16;q++){
        int idx = l*16 + q;
        int o = idx >> 5, d2 = idx & 31;
        float s = Fb[d2];
        #pragma unroll
        for(int ll=0;ll<64;ll++) s += sc[o][ll]*Fw[d2*64+ll];
        out[(size_t)n*1024 + o*32 + d2] = tanhf(s);
    }
}

extern "C" void kernel_launch(void* const* d_in, const int* in_sizes, int n_in,
                              void* d_out, int out_size)
{
    const float* inputs = (const float*)d_in[0];
    const float* Wih0 = (const float*)d_in[1];
    const float* Whh0 = (const float*)d_in[2];
    const float* bih0 = (const float*)d_in[3];
    const float* bhh0 = (const float*)d_in[4];
    const float* Wih1 = (const float*)d_in[5];
    const float* Whh1 = (const float*)d_in[6];
    const float* bih1 = (const float*)d_in[7];
    const float* bhh1 = (const float*)d_in[8];
    const float* A_w  = (const float*)d_in[9];
    const float* A_b  = (const float*)d_in[10];
    const float* g0_Wl = (const float*)d_in[11];
    const float* g0_bl = (const float*)d_in[12];
    const float* g0_Wr = (const float*)d_in[13];
    const float* g0_br = (const float*)d_in[14];
    const float* g0_att = (const float*)d_in[15];
    const float* g0_bias = (const float*)d_in[16];
    const float* g1_Wl = (const float*)d_in[17];
    const float* g1_bl = (const float*)d_in[18];
    const float* g1_Wr = (const float*)d_in[19];
    const float* g1_br = (const float*)d_in[20];
    const float* g1_att = (const float*)d_in[21];
    const float* g1_bias = (const float*)d_in[22];
    const float* W_caps = (const float*)d_in[23];
    const float* F_w = (const float*)d_in[24];
    const float* F_b = (const float*)d_in[25];
    float* out = (float*)d_out;

    float *Xs,*Gi,*H0,*Emb,*hz,*P,*XN,*XL,*XR,*G0,*G1,*FUS,*PR;
    cudaGetSymbolAddress((void**)&Xs,  g_Xs);
    cudaGetSymbolAddress((void**)&Gi,  g_Gi);
    cudaGetSymbolAddress((void**)&H0,  g_H0);
    cudaGetSymbolAddress((void**)&Emb, g_Emb);
    cudaGetSymbolAddress((void**)&hz,  g_hz);
    cudaGetSymbolAddress((void**)&P,   g_P);
    cudaGetSymbolAddress((void**)&XN,  g_XN);
    cudaGetSymbolAddress((void**)&XL,  g_XL);
    cudaGetSymbolAddress((void**)&XR,  g_XR);
    cudaGetSymbolAddress((void**)&G0,  g_G0);
    cudaGetSymbolAddress((void**)&G1,  g_G1);
    cudaGetSymbolAddress((void**)&FUS, g_FUS);
    cudaGetSymbolAddress((void**)&PR,  g_PR);

    const int NTOT = Bc*Tc*Fc;
    k_zero<<<(Tc*Fc+255)/256, 256>>>(hz, Tc*Fc);
    k_sanitize<<<(NTOT+255)/256, 256>>>(inputs, Xs, NTOT);

    // layer 0
    k_sgemm<<<dim3(G3/128, (Bc*Tc)/128), 256>>>(Xs, Wih0, bih0, Gi, G3, Fc);
    for(int b=0;b<Bc;b++){
        const float* hp = b ? (H0 + (size_t)(b-1)*Tc*Fc) : hz;
        k_rgemm<<<dim3(48,4), 256>>>(hp, Whh0, P);
        k_gate<<<256, 256>>>(b, P, Gi, bhh0, hp, H0);
    }
    // layer 1
    k_sgemm<<<dim3(G3/128, (Bc*Tc)/128), 256>>>(H0, Wih1, bih1, Gi, G3, Fc);
    for(int b=0;b<Bc;b++){
        const float* hp = b ? (Emb + (size_t)(b-1)*Tc*Fc) : hz;
        k_rgemm<<<dim3(48,4), 256>>>(hp, Whh1, P);
        k_gate<<<256, 256>>>(b, P, Gi, bhh1, hp, Emb);
    }
    // attention -> node features
    k_attn<<<(Bc*Fc)/256, 256>>>(Emb, A_w, A_b, XN);
    // GAT layer 0
    k_lin64<<<Nn/64, 256>>>(XN, g0_Wl, g0_bl, g0_Wr, g0_br, XL, XR);
    k_gat<<<1024, 128>>>(XL, XR, g0_att, g0_bias, G0);
    // GAT layer 1
    k_lin64<<<Nn/64, 256>>>(G0, g1_Wl, g1_bl, g1_Wr, g1_br, XL, XR);
    k_gat<<<1024, 128>>>(XL, XR, g1_att, g1_bias, G1);
    // fusion + capsule priors
    k_fus<<<(Nn*128)/256, 256>>>(XN, G0, G1, FUS);
    k_sgemm<<<dim3(2048/128, Nn/128), 256>>>(FUS, W_caps, nullptr, PR, 2048, 128);
    // routing + head
    k_route<<<Bc, 64>>>(PR, F_w, F_b, out);
}

// round 3
// speedup vs baseline: 1.1855x; 1.1855x over previous
#include <cuda_runtime.h>
#include <cuda_bf16.h>
#include <math.h>
#include <stdint.h>

#define Bc 128
#define Tc 32
#define Fc 2048
#define G3 6144
#define Hc 64
#define Nn 4096
#define KSPLIT 16
#define KCHUNK 128   // Fc / KSPLIT

// ---- static scratch (no cudaMalloc allowed) ----
__device__ float g_Xs[Bc*Tc*Fc];
__device__ float g_Gi[(size_t)Bc*Tc*G3];
__device__ float g_H0[Bc*Tc*Fc];
__device__ float g_Emb[Bc*Tc*Fc];
__device__ float g_hz[Tc*Fc];
__device__ float g_P[(size_t)KSPLIT*Tc*G3];
__device__ float g_XN[Nn*Hc];
__device__ float g_XL[Nn*Hc];
__device__ float g_XR[Nn*Hc];
__device__ float g_G0[Nn*Hc];
__device__ float g_G1[Nn*Hc];
__device__ float g_FUS[Nn*2*Hc];
__device__ float g_PR[(size_t)Nn*2048];

// ---- packed f32x2 helpers ----
__device__ __forceinline__ unsigned long long pk2(float x){
    unsigned long long r; asm("mov.b64 %0,{%1,%1};" : "=l"(r) : "f"(x)); return r;
}
__device__ __forceinline__ void ffma2(unsigned long long& d, unsigned long long a, unsigned long long b){
    asm("fma.rn.f32x2 %0,%1,%2,%0;" : "+l"(d) : "l"(a), "l"(b));
}
__device__ __forceinline__ float2 up2(unsigned long long v){
    float2 r; asm("mov.b64 {%0,%1},%2;" : "=f"(r.x), "=f"(r.y) : "l"(v)); return r;
}

// ---- utility ----
__global__ void k_zero(float* p, int n){ int i=blockIdx.x*256+threadIdx.x; if(i<n) p[i]=0.f; }

__global__ void k_sanitize(const float* __restrict__ in, float* __restrict__ out, int n){
    int i = blockIdx.x*256 + threadIdx.x;
    if(i<n){
        float v = in[i];
        if (isnan(v)) v = 0.f;
        else if (isinf(v)) v = (v>0.f) ? 1.0f : -3.4028234663852886e38f;
        out[i] = v;
    }
}

// ---- big SGEMM: C[M,N] = A[M,K] @ B[N,K]^T (+bias), 128x128 tile, f32x2 ----
__global__ void __launch_bounds__(256) k_sgemm(const float* __restrict__ A,
                                               const float* __restrict__ Bm,
                                               const float* __restrict__ bias,
                                               float* __restrict__ C,
                                               int Ncols, int K)
{
    __shared__ float As[8][128];
    __shared__ float Bs[8][128];
    const int tid = threadIdx.x;
    const int tx = tid & 15, ty = tid >> 4;
    const int m0 = blockIdx.y*128, n0 = blockIdx.x*128;
    const int lr = tid >> 1, lc = (tid & 1)*4;
    const float* Ap = A + (size_t)(m0+lr)*K + lc;
    const float* Bp = Bm + (size_t)(n0+lr)*K + lc;

    unsigned long long acc[8][4];
    #pragma unroll
    for(int i=0;i<8;i++)
        #pragma unroll
        for(int j=0;j<4;j++) acc[i][j]=0ULL;

    for(int k0=0;k0<K;k0+=8){
        float4 av = *(const float4*)(Ap + k0);
        float4 bv = *(const float4*)(Bp + k0);
        __syncthreads();
        As[lc+0][lr]=av.x; As[lc+1][lr]=av.y; As[lc+2][lr]=av.z; As[lc+3][lr]=av.w;
        Bs[lc+0][lr]=bv.x; Bs[lc+1][lr]=bv.y; Bs[lc+2][lr]=bv.z; Bs[lc+3][lr]=bv.w;
        __syncthreads();
        #pragma unroll
        for(int k=0;k<8;k++){
            float4 a0 = *(const float4*)&As[k][ty*8];
            float4 a1 = *(const float4*)&As[k][ty*8+4];
            ulonglong2 b01 = *(const ulonglong2*)&Bs[k][tx*8];
            ulonglong2 b23 = *(const ulonglong2*)&Bs[k][tx*8+4];
            unsigned long long aa[8];
            aa[0]=pk2(a0.x); aa[1]=pk2(a0.y); aa[2]=pk2(a0.z); aa[3]=pk2(a0.w);
            aa[4]=pk2(a1.x); aa[5]=pk2(a1.y); aa[6]=pk2(a1.z); aa[7]=pk2(a1.w);
            #pragma unroll
            for(int i=0;i<8;i++){
                ffma2(acc[i][0], aa[i], b01.x);
                ffma2(acc[i][1], aa[i], b01.y);
                ffma2(acc[i][2], aa[i], b23.x);
                ffma2(acc[i][3], aa[i], b23.y);
            }
        }
    }
    #pragma unroll
    for(int i=0;i<8;i++){
        int row = m0 + ty*8 + i;
        #pragma unroll
        for(int j=0;j<4;j++){
            float2 v = up2(acc[i][j]);
            int col = n0 + tx*8 + j*2;
            float b0 = bias ? bias[col]   : 0.f;
            float b1 = bias ? bias[col+1] : 0.f;
            C[(size_t)row*Ncols + col]   = v.x + b0;
            C[(size_t)row*Ncols + col+1] = v.y + b1;
        }
    }
}

// ---- recurrent GEMM: P[ks][32][6144] partials of H[32,2048] @ W[6144,2048]^T ----
// grid (48, KSPLIT), block 256, KCHUNK=128 per CTA -> 768 CTAs
__global__ void __launch_bounds__(256) k_rgemm(const float* __restrict__ H,
                                               const float* __restrict__ W,
                                               float* __restrict__ P)
{
    __shared__ float As[16][32];
    __shared__ float Bs[16][128];
    const int tid = threadIdx.x;
    const int cg = tid & 15, rg = tid >> 4;   // rg 0..15 (2 rows), cg 0..15 (8 cols)
    const int n0 = blockIdx.x * 128;
    const int kbase = blockIdx.y * KCHUNK;

    unsigned long long acc[2][4];
    #pragma unroll
    for(int i=0;i<2;i++)
        #pragma unroll
        for(int j=0;j<4;j++) acc[i][j]=0ULL;

    const int hr = tid>>2, hq = tid&3;            // H load: threads 0..127
    const int wr0 = tid>>2, wq0 = tid&3;          // W load part 0
    const int wr1 = (tid+256)>>2, wq1 = tid&3;    // W load part 1

    #pragma unroll 1
    for(int k0=0;k0<KCHUNK;k0+=16){
        float4 va;
        if(tid < 128)
            va = *(const float4*)(H + (size_t)hr*Fc + kbase + k0 + hq*4);
        float4 vb0 = *(const float4*)(W + (size_t)(n0+wr0)*Fc + kbase + k0 + wq0*4);
        float4 vb1 = *(const float4*)(W + (size_t)(n0+wr1)*Fc + kbase + k0 + wq1*4);
        __syncthreads();
        if(tid < 128){
            As[hq*4+0][hr]=va.x; As[hq*4+1][hr]=va.y; As[hq*4+2][hr]=va.z; As[hq*4+3][hr]=va.w;
        }
        Bs[wq0*4+0][wr0]=vb0.x; Bs[wq0*4+1][wr0]=vb0.y; Bs[wq0*4+2][wr0]=vb0.z; Bs[wq0*4+3][wr0]=vb0.w;
        Bs[wq1*4+0][wr1]=vb1.x; Bs[wq1*4+1][wr1]=vb1.y; Bs[wq1*4+2][wr1]=vb1.z; Bs[wq1*4+3][wr1]=vb1.w;
        __syncthreads();
        #pragma unroll
        for(int k=0;k<16;k++){
            unsigned long long a0 = pk2(As[k][rg*2]);
            unsigned long long a1 = pk2(As[k][rg*2+1]);
            ulonglong2 b01 = *(const ulonglong2*)&Bs[k][cg*8];
            ulonglong2 b23 = *(const ulonglong2*)&Bs[k][cg*8+4];
            ffma2(acc[0][0], a0, b01.x); ffma2(acc[0][1], a0, b01.y);
            ffma2(acc[0][2], a0, b23.x); ffma2(acc[0][3], a0, b23.y);
            ffma2(acc[1][0], a1, b01.x); ffma2(acc[1][1], a1, b01.y);
            ffma2(acc[1][2], a1, b23.x); ffma2(acc[1][3], a1, b23.y);
        }
    }
    float* Pb = P + (size_t)blockIdx.y*Tc*G3;
    #pragma unroll
    for(int i=0;i<2;i++){
        int row = rg*2 + i;
        #pragma unroll
        for(int j=0;j<4;j++){
            float2 v = up2(acc[i][j]);
            int col = n0 + cg*8 + j*2;
            Pb[(size_t)row*G3 + col]   = v.x;
            Pb[(size_t)row*G3 + col+1] = v.y;
        }
    }
}

// ---- GRU gate fuse: combine K-split partials + input gates + biases ----
__global__ void __launch_bounds__(256) k_gate(int b,
                                              const float* __restrict__ P,
                                              const float* __restrict__ Gi,
                                              const float* __restrict__ bhh,
                                              const float* __restrict__ Hprev,
                                              float* __restrict__ Hall)
{
    int i = blockIdx.x*256 + threadIdx.x;  // 65536 = 32*2048
    int row = i >> 11, j = i & 2047;
    float gr=0.f, gz=0.f, gn=0.f;
    #pragma unroll
    for(int ks=0;ks<KSPLIT;ks++){
        const float* p = P + ((size_t)ks*Tc + row)*G3;
        gr += p[j]; gz += p[2048+j]; gn += p[4096+j];
    }
    const float* gi = Gi + ((size_t)b*Tc + row)*G3;
    float r = 1.f/(1.f + expf(-(gi[j]      + gr + bhh[j])));
    float z = 1.f/(1.f + expf(-(gi[2048+j] + gz + bhh[2048+j])));
    float n = tanhf(gi[4096+j] + r*(gn + bhh[4096+j]));
    float h = Hprev[(size_t)row*Fc + j];
    Hall[((size_t)b*Tc + row)*Fc + j] = (1.f - z)*n + z*h;
}

// ---- temporal attention over T=32 per (b,f) ----
__global__ void __launch_bounds__(256) k_attn(const float* __restrict__ Emb,
                                              const float* __restrict__ Aw,
                                              const float* __restrict__ Ab,
                                              float* __restrict__ XN)
{
    __shared__ float sW[32][33];
    __shared__ float sB[32];
    int tid = threadIdx.x;
    for(int i=tid;i<1024;i+=256) sW[i>>5][i&31] = Aw[i];
    if(tid<32) sB[tid]=Ab[tid];
    __syncthreads();
    int g = blockIdx.x*256 + tid;        // b*2048 + f
    int b = g >> 11, f = g & 2047;
    float tA[32];
    #pragma unroll
    for(int t=0;t<32;t++) tA[t] = tanhf(Emb[((size_t)b*32 + t)*Fc + f]);
    float mx = -1e30f, aw[32];
    #pragma unroll
    for(int t2=0;t2<32;t2++){
        float s = sB[t2];
        #pragma unroll
        for(int t=0;t<32;t++) s += tA[t]*sW[t2][t];
        aw[t2]=s; mx = fmaxf(mx, s);
    }
    float den=0.f, num=0.f;
    #pragma unroll
    for(int t=0;t<32;t++){ float e = expf(aw[t]-mx); den += e; num += e*tA[t]; }
    XN[g] = tanhf(num/den);
}

// ---- GAT projections: XL = X@Wl^T+bl, XR = X@Wr^T+br (64x64) ----
__global__ void __launch_bounds__(256) k_lin64(const float* __restrict__ X,
                                               const float* __restrict__ Wl, const float* __restrict__ bl,
                                               const float* __restrict__ Wr, const float* __restrict__ br,
                                               float* __restrict__ XL, float* __restrict__ XR)
{
    __shared__ float sX[64][65];
    __shared__ float sW[64][65];
    int tid = threadIdx.x;
    int r0 = blockIdx.x*64;
    for(int i=tid;i<4096;i+=256){ int r=i>>6, c=i&63; sX[r][c]=X[(size_t)(r0+r)*64+c]; }
    for(int i=tid;i<4096;i+=256){ int r=i>>6, c=i&63; sW[r][c]=Wl[i]; }
    __syncthreads();
    int r = tid & 63, cq = tid >> 6;
    #pragma unroll 4
    for(int cc=0; cc<16; cc++){
        int c = cq*16 + cc;
        float s = bl[c];
        #pragma unroll
        for(int k=0;k<64;k++) s += sX[r][k]*sW[c][k];
        XL[(size_t)(r0+r)*64 + c] = s;
    }
    __syncthreads();
    for(int i=tid;i<4096;i+=256){ int rr=i>>6, c=i&63; sW[rr][c]=Wr[i]; }
    __syncthreads();
    #pragma unroll 4
    for(int cc=0; cc<16; cc++){
        int c = cq*16 + cc;
        float s = br[c];
        #pragma unroll
        for(int k=0;k<64;k++) s += sX[r][k]*sW[c][k];
        XR[(size_t)(r0+r)*64 + c] = s;
    }
}

// ---- GATv2 on dense 32x32 block graph; one warp per dst node; tanh output ----
__global__ void __launch_bounds__(128) k_gat(const float* __restrict__ XL,
                                             const float* __restrict__ XR,
                                             const float* __restrict__ att,
                                             const float* __restrict__ bias,
                                             float* __restrict__ OUT)
{
    int w = threadIdx.x >> 5, lane = threadIdx.x & 31;
    int g = blockIdx.x >> 3;
    int d = ((blockIdx.x & 7) << 2) + w;
    int nd = g*32 + d;
    float xr0 = XR[(size_t)nd*64 + lane];
    float xr1 = XR[(size_t)nd*64 + 32 + lane];
    float a0 = att[lane], a1 = att[lane+32];
    const float* xlg = XL + (size_t)g*32*64;
    float lg[32];
    #pragma unroll
    for(int s=0;s<32;s++){
        float u = xlg[s*64 + lane]      + xr0;
        float v = xlg[s*64 + 32 + lane] + xr1;
        u = u>0.f ? u : 0.2f*u;
        v = v>0.f ? v : 0.2f*v;
        float t = u*a0 + v*a1;
        #pragma unroll
        for(int o=16;o>0;o>>=1) t += __shfl_xor_sync(0xffffffffu, t, o);
        lg[s] = t;
    }
    float m = -1e30f;
    #pragma unroll
    for(int s=0;s<32;s++) m = fmaxf(m, lg[s]);
    float den = 0.f;
    #pragma unroll
    for(int s=0;s<32;s++){ lg[s] = expf(lg[s]-m); den += lg[s]; }
    float inv = 1.f/den, o0=0.f, o1=0.f;
    #pragma unroll
    for(int s=0;s<32;s++){
        float al = lg[s]*inv;
        o0 += al * xlg[s*64 + lane];
        o1 += al * xlg[s*64 + 32 + lane];
    }
    OUT[(size_t)nd*64 + lane]      = tanhf(o0 + bias[lane]);
    OUT[(size_t)nd*64 + 32 + lane] = tanhf(o1 + bias[lane+32]);
}

// ---- fusion concat ----
__global__ void k_fus(const float* __restrict__ XN, const float* __restrict__ G0,
                      const float* __restrict__ G1, float* __restrict__ FUS)
{
    int i = blockIdx.x*256 + threadIdx.x;  // 4096*128
    int n = i >> 7, q = i & 127;
    FUS[i] = (q < 64) ? XN[(size_t)n*64 + q]
                      : (G0[(size_t)n*64 + q-64] + G1[(size_t)n*64 + q-64]);
}

// ---- capsule routing (3 iters) + final head ----
__global__ void __launch_bounds__(64) k_route(const float* __restrict__ PR,
                                              const float* __restrict__ Fw,
                                              const float* __restrict__ Fb,
                                              float* __restrict__ out)
{
    int n = blockIdx.x, l = threadIdx.x;
    const float* base = PR + (size_t)n*65536 + l;   // idx: c*2048 + o*64
    float o0[32], o1[32], pc[32], te[32];
    #pragma unroll
    for(int o=0;o<32;o++) o0[o]=0.f;
    for(int c=0;c<32;c++){
        const float* pcol = base + (size_t)c*2048;
        #pragma unroll
        for(int o=0;o<32;o++) o0[o] += pcol[o*64];
    }
    #pragma unroll
    for(int o=0;o<32;o++){ o0[o] *= (1.f/32.f); o1[o]=0.f; }
    for(int c=0;c<32;c++){
        const float* pcol = base + (size_t)c*2048;
        float m = -1e30f;
        #pragma unroll
        for(int o=0;o<32;o++){ pc[o]=pcol[o*64]; float lgv = pc[o]*o0[o]; te[o]=lgv; m = fmaxf(m,lgv); }
        float den=0.f;
        #pragma unroll
        for(int o=0;o<32;o++){ te[o]=expf(te[o]-m); den+=te[o]; }
        float inv = 1.f/den;
        #pragma unroll
        for(int o=0;o<32;o++) o1[o] += te[o]*inv*pc[o];
    }
    #pragma unroll
    for(int o=0;o<32;o++){ o0[o] += o1[o]; o1[o]=0.f; }
    for(int c=0;c<32;c++){
        const float* pcol = base + (size_t)c*2048;
        float m = -1e30f;
        #pragma unroll
        for(int o=0;o<32;o++){ pc[o]=pcol[o*64]; float lgv = pc[o]*o0[o]; te[o]=lgv; m = fmaxf(m,lgv); }
        float den=0.f;
        #pragma unroll
        for(int o=0;o<32;o++){ te[o]=expf(te[o]-m); den+=te[o]; }
        float inv = 1.f/den;
        #pragma unroll
        for(int o=0;o<32;o++) o1[o] += te[o]*inv*pc[o];
    }
    __shared__ float sc[32][65];
    #pragma unroll
    for(int o=0;o<32;o++) sc[o][l] = tanhf(o1[o]);
    __syncthreads();
    for(int q=0;q<16;q++){
        int idx = l*16 + q;
        int o = idx >> 5, d2 = idx & 31;
        float s = Fb[d2];
        #pragma unroll
        for(int ll=0;ll<64;ll++) s += sc[o][ll]*Fw[d2*64+ll];
        out[(size_t)n*1024 + o*32 + d2] = tanhf(s);
    }
}

extern "C" void kernel_launch(void* const* d_in, const int* in_sizes, int n_in,
                              void* d_out, int out_size)
{
    const float* inputs = (const float*)d_in[0];
    const float* Wih0 = (const float*)d_in[1];
    const float* Whh0 = (const float*)d_in[2];
    const float* bih0 = (const float*)d_in[3];
    const float* bhh0 = (const float*)d_in[4];
    const float* Wih1 = (const float*)d_in[5];
    const float* Whh1 = (const float*)d_in[6];
    const float* bih1 = (const float*)d_in[7];
    const float* bhh1 = (const float*)d_in[8];
    const float* A_w  = (const float*)d_in[9];
    const float* A_b  = (const float*)d_in[10];
    const float* g0_Wl = (const float*)d_in[11];
    const float* g0_bl = (const float*)d_in[12];
    const float* g0_Wr = (const float*)d_in[13];
    const float* g0_br = (const float*)d_in[14];
    const float* g0_att = (const float*)d_in[15];
    const float* g0_bias = (const float*)d_in[16];
    const float* g1_Wl = (const float*)d_in[17];
    const float* g1_bl = (const float*)d_in[18];
    const float* g1_Wr = (const float*)d_in[19];
    const float* g1_br = (const float*)d_in[20];
    const float* g1_att = (const float*)d_in[21];
    const float* g1_bias = (const float*)d_in[22];
    const float* W_caps = (const float*)d_in[23];
    const float* F_w = (const float*)d_in[24];
    const float* F_b = (const float*)d_in[25];
    float* out = (float*)d_out;

    float *Xs,*Gi,*H0,*Emb,*hz,*P,*XN,*XL,*XR,*G0,*G1,*FUS,*PR;
    cudaGetSymbolAddress((void**)&Xs,  g_Xs);
    cudaGetSymbolAddress((void**)&Gi,  g_Gi);
    cudaGetSymbolAddress((void**)&H0,  g_H0);
    cudaGetSymbolAddress((void**)&Emb, g_Emb);
    cudaGetSymbolAddress((void**)&hz,  g_hz);
    cudaGetSymbolAddress((void**)&P,   g_P);
    cudaGetSymbolAddress((void**)&XN,  g_XN);
    cudaGetSymbolAddress((void**)&XL,  g_XL);
    cudaGetSymbolAddress((void**)&XR,  g_XR);
    cudaGetSymbolAddress((void**)&G0,  g_G0);
    cudaGetSymbolAddress((void**)&G1,  g_G1);
    cudaGetSymbolAddress((void**)&FUS, g_FUS);
    cudaGetSymbolAddress((void**)&PR,  g_PR);

    const int NTOT = Bc*Tc*Fc;
    k_zero<<<(Tc*Fc+255)/256, 256>>>(hz, Tc*Fc);
    k_sanitize<<<(NTOT+255)/256, 256>>>(inputs, Xs, NTOT);

    // layer 0
    k_sgemm<<<dim3(G3/128, (Bc*Tc)/128), 256>>>(Xs, Wih0, bih0, Gi, G3, Fc);
    for(int b=0;b<Bc;b++){
        const float* hp = b ? (H0 + (size_t)(b-1)*Tc*Fc) : hz;
        k_rgemm<<<dim3(48,KSPLIT), 256>>>(hp, Whh0, P);
        k_gate<<<256, 256>>>(b, P, Gi, bhh0, hp, H0);
    }
    // layer 1
    k_sgemm<<<dim3(G3/128, (Bc*Tc)/128), 256>>>(H0, Wih1, bih1, Gi, G3, Fc);
    for(int b=0;b<Bc;b++){
        const float* hp = b ? (Emb + (size_t)(b-1)*Tc*Fc) : hz;
        k_rgemm<<<dim3(48,KSPLIT), 256>>>(hp, Whh1, P);
        k_gate<<<256, 256>>>(b, P, Gi, bhh1, hp, Emb);
    }
    // attention -> node features
    k_attn<<<(Bc*Fc)/256, 256>>>(Emb, A_w, A_b, XN);
    // GAT layer 0
    k_lin64<<<Nn/64, 256>>>(XN, g0_Wl, g0_bl, g0_Wr, g0_br, XL, XR);
    k_gat<<<1024, 128>>>(XL, XR, g0_att, g0_bias, G0);
    // GAT layer 1
    k_lin64<<<Nn/64, 256>>>(G0, g1_Wl, g1_bl, g1_Wr, g1_br, XL, XR);
    k_gat<<<1024, 128>>>(XL, XR, g1_att, g1_bias, G1);
    // fusion + capsule priors
    k_fus<<<(Nn*128)/256, 256>>>(XN, G0, G1, FUS);
    k_sgemm<<<dim3(2048/128, Nn/128), 256>>>(FUS, W_caps, nullptr, PR, 2048, 128);
    // routing + head
    k_route<<<Bc, 64>>>(PR, F_w, F_b, out);
}

// round 4
// speedup vs baseline: 2.0448x; 1.7249x over previous
#include <cuda_runtime.h>
#include <cuda_bf16.h>
#include <math.h>
#include <stdint.h>

#define Bc 128
#define Tc 32
#define Fc 2048
#define G3 6144
#define Hc 64
#define Nn 4096
#define KSPLIT 16
#define KCHUNK 128   // Fc / KSPLIT
#define KT 16
#define NKT (KCHUNK/KT)
#define NTILE 256

// ---- static scratch (no cudaMalloc allowed) ----
__device__ float g_Xs[Bc*Tc*Fc];
__device__ float g_Gi[(size_t)Bc*Tc*G3];
__device__ float g_H0[Bc*Tc*Fc];
__device__ float g_Emb[Bc*Tc*Fc];
__device__ float g_hz[Tc*Fc];
__device__ float g_P[(size_t)KSPLIT*Tc*G3];
__device__ float g_XN[Nn*Hc];
__device__ float g_XL[Nn*Hc];
__device__ float g_XR[Nn*Hc];
__device__ float g_G0[Nn*Hc];
__device__ float g_G1[Nn*Hc];
__device__ float g_FUS[Nn*2*Hc];
__device__ float g_PR[(size_t)Nn*2048];

// ---- packed f32x2 helpers ----
__device__ __forceinline__ unsigned long long pk2(float x){
    unsigned long long r; asm("mov.b64 %0,{%1,%1};" : "=l"(r) : "f"(x)); return r;
}
__device__ __forceinline__ void ffma2(unsigned long long& d, unsigned long long a, unsigned long long b){
    asm("fma.rn.f32x2 %0,%1,%2,%0;" : "+l"(d) : "l"(a), "l"(b));
}
__device__ __forceinline__ float2 up2(unsigned long long v){
    float2 r; asm("mov.b64 {%0,%1},%2;" : "=f"(r.x), "=f"(r.y) : "l"(v)); return r;
}

// ---- utility ----
__global__ void k_zero(float* p, int n){ int i=blockIdx.x*256+threadIdx.x; if(i<n) p[i]=0.f; }

__global__ void k_sanitize(const float* __restrict__ in, float* __restrict__ out, int n){
    int i = blockIdx.x*256 + threadIdx.x;
    if(i<n){
        float v = in[i];
        if (isnan(v)) v = 0.f;
        else if (isinf(v)) v = (v>0.f) ? 1.0f : -3.4028234663852886e38f;
        out[i] = v;
    }
}

// ---- big SGEMM: C[M,N] = A[M,K] @ B[N,K]^T (+bias), 128x128 tile, f32x2 ----
__global__ void __launch_bounds__(256) k_sgemm(const float* __restrict__ A,
                                               const float* __restrict__ Bm,
                                               const float* __restrict__ bias,
                                               float* __restrict__ C,
                                               int Ncols, int K)
{
    __shared__ float As[8][128];
    __shared__ float Bs[8][128];
    const int tid = threadIdx.x;
    const int tx = tid & 15, ty = tid >> 4;
    const int m0 = blockIdx.y*128, n0 = blockIdx.x*128;
    const int lr = tid >> 1, lc = (tid & 1)*4;
    const float* Ap = A + (size_t)(m0+lr)*K + lc;
    const float* Bp = Bm + (size_t)(n0+lr)*K + lc;

    unsigned long long acc[8][4];
    #pragma unroll
    for(int i=0;i<8;i++)
        #pragma unroll
        for(int j=0;j<4;j++) acc[i][j]=0ULL;

    for(int k0=0;k0<K;k0+=8){
        float4 av = *(const float4*)(Ap + k0);
        float4 bv = *(const float4*)(Bp + k0);
        __syncthreads();
        As[lc+0][lr]=av.x; As[lc+1][lr]=av.y; As[lc+2][lr]=av.z; As[lc+3][lr]=av.w;
        Bs[lc+0][lr]=bv.x; Bs[lc+1][lr]=bv.y; Bs[lc+2][lr]=bv.z; Bs[lc+3][lr]=bv.w;
        __syncthreads();
        #pragma unroll
        for(int k=0;k<8;k++){
            float4 a0 = *(const float4*)&As[k][ty*8];
            float4 a1 = *(const float4*)&As[k][ty*8+4];
            ulonglong2 b01 = *(const ulonglong2*)&Bs[k][tx*8];
            ulonglong2 b23 = *(const ulonglong2*)&Bs[k][tx*8+4];
            unsigned long long aa[8];
            aa[0]=pk2(a0.x); aa[1]=pk2(a0.y); aa[2]=pk2(a0.z); aa[3]=pk2(a0.w);
            aa[4]=pk2(a1.x); aa[5]=pk2(a1.y); aa[6]=pk2(a1.z); aa[7]=pk2(a1.w);
            #pragma unroll
            for(int i=0;i<8;i++){
                ffma2(acc[i][0], aa[i], b01.x);
                ffma2(acc[i][1], aa[i], b01.y);
                ffma2(acc[i][2], aa[i], b23.x);
                ffma2(acc[i][3], aa[i], b23.y);
            }
        }
    }
    #pragma unroll
    for(int i=0;i<8;i++){
        int row = m0 + ty*8 + i;
        #pragma unroll
        for(int j=0;j<4;j++){
            float2 v = up2(acc[i][j]);
            int col = n0 + tx*8 + j*2;
            float b0 = bias ? bias[col]   : 0.f;
            float b1 = bias ? bias[col+1] : 0.f;
            C[(size_t)row*Ncols + col]   = v.x + b0;
            C[(size_t)row*Ncols + col+1] = v.y + b1;
        }
    }
}

// ---- recurrent GEMM: P[ks][32][6144] partials of H[32,2048] @ W[6144,2048]^T ----
// tile M=32 x N=256, KCHUNK=128, double-buffered, f32x2 row-pair accumulators.
// grid (24, 16), block 256
__global__ void __launch_bounds__(256) k_rgemm(const float* __restrict__ H,
                                               const float* __restrict__ W,
                                               float* __restrict__ P)
{
    __shared__ float As[2][KT][36];
    __shared__ float Bs[2][KT][260];
    const int tid = threadIdx.x;
    const int cg = tid & 63;        // 64 col groups x 4 cols
    const int rg = tid >> 6;        // 4 row groups x 8 rows
    const int n0 = blockIdx.x * NTILE;
    const int kbase = blockIdx.y * KCHUNK;

    const int lr = tid >> 2;        // 0..63
    const int lq = tid & 3;         // k-quad

    unsigned long long acc[4][4];
    #pragma unroll
    for(int i=0;i<4;i++)
        #pragma unroll
        for(int j=0;j<4;j++) acc[i][j]=0ULL;

    float4 stA; float4 stB[4];

    // prologue: load ktile 0
    {
        const int gk = kbase;
        if(tid < 128) stA = *(const float4*)(H + (size_t)lr*Fc + gk + lq*4);
        #pragma unroll
        for(int p=0;p<4;p++)
            stB[p] = *(const float4*)(W + (size_t)(n0 + p*64 + lr)*Fc + gk + lq*4);
        if(tid < 128){
            As[0][lq*4+0][lr]=stA.x; As[0][lq*4+1][lr]=stA.y;
            As[0][lq*4+2][lr]=stA.z; As[0][lq*4+3][lr]=stA.w;
        }
        #pragma unroll
        for(int p=0;p<4;p++){
            int col = p*64 + lr;
            Bs[0][lq*4+0][col]=stB[p].x; Bs[0][lq*4+1][col]=stB[p].y;
            Bs[0][lq*4+2][col]=stB[p].z; Bs[0][lq*4+3][col]=stB[p].w;
        }
    }

    int buf = 0;
    #pragma unroll 1
    for(int t=0;t<NKT;t++){
        __syncthreads();
        if(t+1 < NKT){
            const int gk = kbase + (t+1)*KT;
            if(tid < 128) stA = *(const float4*)(H + (size_t)lr*Fc + gk + lq*4);
            #pragma unroll
            for(int p=0;p<4;p++)
                stB[p] = *(const float4*)(W + (size_t)(n0 + p*64 + lr)*Fc + gk + lq*4);
        }
        // compute current buffer
        #pragma unroll
        for(int k=0;k<KT;k++){
            ulonglong2 a01 = *(const ulonglong2*)&As[buf][k][rg*8];
            ulonglong2 a23 = *(const ulonglong2*)&As[buf][k][rg*8+4];
            float4 bf = *(const float4*)&Bs[buf][k][cg*4];
            unsigned long long b0=pk2(bf.x), b1=pk2(bf.y), b2=pk2(bf.z), b3=pk2(bf.w);
            ffma2(acc[0][0], a01.x, b0); ffma2(acc[0][1], a01.x, b1);
            ffma2(acc[0][2], a01.x, b2); ffma2(acc[0][3], a01.x, b3);
            ffma2(acc[1][0], a01.y, b0); ffma2(acc[1][1], a01.y, b1);
            ffma2(acc[1][2], a01.y, b2); ffma2(acc[1][3], a01.y, b3);
            ffma2(acc[2][0], a23.x, b0); ffma2(acc[2][1], a23.x, b1);
            ffma2(acc[2][2], a23.x, b2); ffma2(acc[2][3], a23.x, b3);
            ffma2(acc[3][0], a23.y, b0); ffma2(acc[3][1], a23.y, b1);
            ffma2(acc[3][2], a23.y, b2); ffma2(acc[3][3], a23.y, b3);
        }
        if(t+1 < NKT){
            int nb = buf^1;
            if(tid < 128){
                As[nb][lq*4+0][lr]=stA.x; As[nb][lq*4+1][lr]=stA.y;
                As[nb][lq*4+2][lr]=stA.z; As[nb][lq*4+3][lr]=stA.w;
            }
            #pragma unroll
            for(int p=0;p<4;p++){
                int col = p*64 + lr;
                Bs[nb][lq*4+0][col]=stB[p].x; Bs[nb][lq*4+1][col]=stB[p].y;
                Bs[nb][lq*4+2][col]=stB[p].z; Bs[nb][lq*4+3][col]=stB[p].w;
            }
        }
        buf ^= 1;
    }

    float* Pb = P + (size_t)blockIdx.y*Tc*G3;
    #pragma unroll
    for(int rp=0;rp<4;rp++){
        int row = rg*8 + rp*2;
        #pragma unroll
        for(int c=0;c<4;c++){
            float2 v = up2(acc[rp][c]);
            int col = n0 + cg*4 + c;
            Pb[(size_t)row*G3 + col]     = v.x;
            Pb[(size_t)(row+1)*G3 + col] = v.y;
        }
    }
}

// ---- GRU gate fuse: combine K-split partials + input gates + biases (float4) ----
__global__ void __launch_bounds__(256) k_gate(int b,
                                              const float* __restrict__ P,
                                              const float* __restrict__ Gi,
                                              const float* __restrict__ bhh,
                                              const float* __restrict__ Hprev,
                                              float* __restrict__ Hall)
{
    int i4 = blockIdx.x*256 + threadIdx.x;   // 16384 quads = 32*2048/4
    int row = i4 >> 9, j = (i4 & 511)*4;
    float4 gr = {0,0,0,0}, gz = {0,0,0,0}, gn = {0,0,0,0};
    #pragma unroll
    for(int ks=0;ks<KSPLIT;ks++){
        const float* p = P + ((size_t)ks*Tc + row)*G3;
        float4 a = *(const float4*)(p + j);
        float4 bv = *(const float4*)(p + 2048 + j);
        float4 c = *(const float4*)(p + 4096 + j);
        gr.x+=a.x; gr.y+=a.y; gr.z+=a.z; gr.w+=a.w;
        gz.x+=bv.x; gz.y+=bv.y; gz.z+=bv.z; gz.w+=bv.w;
        gn.x+=c.x; gn.y+=c.y; gn.z+=c.z; gn.w+=c.w;
    }
    const float* gi = Gi + ((size_t)b*Tc + row)*G3;
    float4 gir = *(const float4*)(gi + j);
    float4 giz = *(const float4*)(gi + 2048 + j);
    float4 gin = *(const float4*)(gi + 4096 + j);
    float4 br = *(const float4*)(bhh + j);
    float4 bz = *(const float4*)(bhh + 2048 + j);
    float4 bn = *(const float4*)(bhh + 4096 + j);
    float4 hp = *(const float4*)(Hprev + (size_t)row*Fc + j);
    float4 ho;
    {
        float r = 1.f/(1.f + expf(-(gir.x + gr.x + br.x)));
        float z = 1.f/(1.f + expf(-(giz.x + gz.x + bz.x)));
        float n = tanhf(gin.x + r*(gn.x + bn.x));
        ho.x = (1.f - z)*n + z*hp.x;
        r = 1.f/(1.f + expf(-(gir.y + gr.y + br.y)));
        z = 1.f/(1.f + expf(-(giz.y + gz.y + bz.y)));
        n = tanhf(gin.y + r*(gn.y + bn.y));
        ho.y = (1.f - z)*n + z*hp.y;
        r = 1.f/(1.f + expf(-(gir.z + gr.z + br.z)));
        z = 1.f/(1.f + expf(-(giz.z + gz.z + bz.z)));
        n = tanhf(gin.z + r*(gn.z + bn.z));
        ho.z = (1.f - z)*n + z*hp.z;
        r = 1.f/(1.f + expf(-(gir.w + gr.w + br.w)));
        z = 1.f/(1.f + expf(-(giz.w + gz.w + bz.w)));
        n = tanhf(gin.w + r*(gn.w + bn.w));
        ho.w = (1.f - z)*n + z*hp.w;
    }
    *(float4*)(Hall + ((size_t)b*Tc + row)*Fc + j) = ho;
}

// ---- temporal attention over T=32 per (b,f) ----
__global__ void __launch_bounds__(256) k_attn(const float* __restrict__ Emb,
                                              const float* __restrict__ Aw,
                                              const float* __restrict__ Ab,
                                              float* __restrict__ XN)
{
    __shared__ float sW[32][33];
    __shared__ float sB[32];
    int tid = threadIdx.x;
    for(int i=tid;i<1024;i+=256) sW[i>>5][i&31] = Aw[i];
    if(tid<32) sB[tid]=Ab[tid];
    __syncthreads();
    int g = blockIdx.x*256 + tid;        // b*2048 + f
    int b = g >> 11, f = g & 2047;
    float tA[32];
    #pragma unroll
    for(int t=0;t<32;t++) tA[t] = tanhf(Emb[((size_t)b*32 + t)*Fc + f]);
    float mx = -1e30f, aw[32];
    #pragma unroll
    for(int t2=0;t2<32;t2++){
        float s = sB[t2];
        #pragma unroll
        for(int t=0;t<32;t++) s += tA[t]*sW[t2][t];
        aw[t2]=s; mx = fmaxf(mx, s);
    }
    float den=0.f, num=0.f;
    #pragma unroll
    for(int t=0;t<32;t++){ float e = expf(aw[t]-mx); den += e; num += e*tA[t]; }
    XN[g] = tanhf(num/den);
}

// ---- GAT projections: XL = X@Wl^T+bl, XR = X@Wr^T+br (64x64) ----
__global__ void __launch_bounds__(256) k_lin64(const float* __restrict__ X,
                                               const float* __restrict__ Wl, const float* __restrict__ bl,
                                               const float* __restrict__ Wr, const float* __restrict__ br,
                                               float* __restrict__ XL, float* __restrict__ XR)
{
    __shared__ float sX[64][65];
    __shared__ float sW[64][65];
    int tid = threadIdx.x;
    int r0 = blockIdx.x*64;
    for(int i=tid;i<4096;i+=256){ int r=i>>6, c=i&63; sX[r][c]=X[(size_t)(r0+r)*64+c]; }
    for(int i=tid;i<4096;i+=256){ int r=i>>6, c=i&63; sW[r][c]=Wl[i]; }
    __syncthreads();
    int r = tid & 63, cq = tid >> 6;
    #pragma unroll 4
    for(int cc=0; cc<16; cc++){
        int c = cq*16 + cc;
        float s = bl[c];
        #pragma unroll
        for(int k=0;k<64;k++) s += sX[r][k]*sW[c][k];
        XL[(size_t)(r0+r)*64 + c] = s;
    }
    __syncthreads();
    for(int i=tid;i<4096;i+=256){ int rr=i>>6, c=i&63; sW[rr][c]=Wr[i]; }
    __syncthreads();
    #pragma unroll 4
    for(int cc=0; cc<16; cc++){
        int c = cq*16 + cc;
        float s = br[c];
        #pragma unroll
        for(int k=0;k<64;k++) s += sX[r][k]*sW[c][k];
        XR[(size_t)(r0+r)*64 + c] = s;
    }
}

// ---- GATv2 on dense 32x32 block graph; one warp per dst node; tanh output ----
__global__ void __launch_bounds__(128) k_gat(const float* __restrict__ XL,
                                             const float* __restrict__ XR,
                                             const float* __restrict__ att,
                                             const float* __restrict__ bias,
                                             float* __restrict__ OUT)
{
    int w = threadIdx.x >> 5, lane = threadIdx.x & 31;
    int g = blockIdx.x >> 3;
    int d = ((blockIdx.x & 7) << 2) + w;
    int nd = g*32 + d;
    float xr0 = XR[(size_t)nd*64 + lane];
    float xr1 = XR[(size_t)nd*64 + 32 + lane];
    float a0 = att[lane], a1 = att[lane+32];
    const float* xlg = XL + (size_t)g*32*64;
    float lg[32];
    #pragma unroll
    for(int s=0;s<32;s++){
        float u = xlg[s*64 + lane]      + xr0;
        float v = xlg[s*64 + 32 + lane] + xr1;
        u = u>0.f ? u : 0.2f*u;
        v = v>0.f ? v : 0.2f*v;
        float t = u*a0 + v*a1;
        #pragma unroll
        for(int o=16;o>0;o>>=1) t += __shfl_xor_sync(0xffffffffu, t, o);
        lg[s] = t;
    }
    float m = -1e30f;
    #pragma unroll
    for(int s=0;s<32;s++) m = fmaxf(m, lg[s]);
    float den = 0.f;
    #pragma unroll
    for(int s=0;s<32;s++){ lg[s] = expf(lg[s]-m); den += lg[s]; }
    float inv = 1.f/den, o0=0.f, o1=0.f;
    #pragma unroll
    for(int s=0;s<32;s++){
        float al = lg[s]*inv;
        o0 += al * xlg[s*64 + lane];
        o1 += al * xlg[s*64 + 32 + lane];
    }
    OUT[(size_t)nd*64 + lane]      = tanhf(o0 + bias[lane]);
    OUT[(size_t)nd*64 + 32 + lane] = tanhf(o1 + bias[lane+32]);
}

// ---- fusion concat ----
__global__ void k_fus(const float* __restrict__ XN, const float* __restrict__ G0,
                      const float* __restrict__ G1, float* __restrict__ FUS)
{
    int i = blockIdx.x*256 + threadIdx.x;  // 4096*128
    int n = i >> 7, q = i & 127;
    FUS[i] = (q < 64) ? XN[(size_t)n*64 + q]
                      : (G0[(size_t)n*64 + q-64] + G1[(size_t)n*64 + q-64]);
}

// ---- capsule routing (3 iters) + final head ----
__global__ void __launch_bounds__(64) k_route(const float* __restrict__ PR,
                                              const float* __restrict__ Fw,
                                              const float* __restrict__ Fb,
                                              float* __restrict__ out)
{
    int n = blockIdx.x, l = threadIdx.x;
    const float* base = PR + (size_t)n*65536 + l;   // idx: c*2048 + o*64
    float o0[32], o1[32], pc[32], te[32];
    #pragma unroll
    for(int o=0;o<32;o++) o0[o]=0.f;
    for(int c=0;c<32;c++){
        const float* pcol = base + (size_t)c*2048;
        #pragma unroll
        for(int o=0;o<32;o++) o0[o] += pcol[o*64];
    }
    #pragma unroll
    for(int o=0;o<32;o++){ o0[o] *= (1.f/32.f); o1[o]=0.f; }
    for(int c=0;c<32;c++){
        const float* pcol = base + (size_t)c*2048;
        float m = -1e30f;
        #pragma unroll
        for(int o=0;o<32;o++){ pc[o]=pcol[o*64]; float lgv = pc[o]*o0[o]; te[o]=lgv; m = fmaxf(m,lgv); }
        float den=0.f;
        #pragma unroll
        for(int o=0;o<32;o++){ te[o]=expf(te[o]-m); den+=te[o]; }
        float inv = 1.f/den;
        #pragma unroll
        for(int o=0;o<32;o++) o1[o] += te[o]*inv*pc[o];
    }
    #pragma unroll
    for(int o=0;o<32;o++){ o0[o] += o1[o]; o1[o]=0.f; }
    for(int c=0;c<32;c++){
        const float* pcol = base + (size_t)c*2048;
        float m = -1e30f;
        #pragma unroll
        for(int o=0;o<32;o++){ pc[o]=pcol[o*64]; float lgv = pc[o]*o0[o]; te[o]=lgv; m = fmaxf(m,lgv); }
        float den=0.f;
        #pragma unroll
        for(int o=0;o<32;o++){ te[o]=expf(te[o]-m); den+=te[o]; }
        float inv = 1.f/den;
        #pragma unroll
        for(int o=0;o<32;o++) o1[o] += te[o]*inv*pc[o];
    }
    __shared__ float sc[32][65];
    #pragma unroll
    for(int o=0;o<32;o++) sc[o][l] = tanhf(o1[o]);
    __syncthreads();
    for(int q=0;q<16;q++){
        int idx = l*16 + q;
        int o = idx >> 5, d2 = idx & 31;
        float s = Fb[d2];
        #pragma unroll
        for(int ll=0;ll<64;ll++) s += sc[o][ll]*Fw[d2*64+ll];
        out[(size_t)n*1024 + o*32 + d2] = tanhf(s);
    }
}

extern "C" void kernel_launch(void* const* d_in, const int* in_sizes, int n_in,
                              void* d_out, int out_size)
{
    const float* inputs = (const float*)d_in[0];
    const float* Wih0 = (const float*)d_in[1];
    const float* Whh0 = (const float*)d_in[2];
    const float* bih0 = (const float*)d_in[3];
    const float* bhh0 = (const float*)d_in[4];
    const float* Wih1 = (const float*)d_in[5];
    const float* Whh1 = (const float*)d_in[6];
    const float* bih1 = (const float*)d_in[7];
    const float* bhh1 = (const float*)d_in[8];
    const float* A_w  = (const float*)d_in[9];
    const float* A_b  = (const float*)d_in[10];
    const float* g0_Wl = (const float*)d_in[11];
    const float* g0_bl = (const float*)d_in[12];
    const float* g0_Wr = (const float*)d_in[13];
    const float* g0_br = (const float*)d_in[14];
    const float* g0_att = (const float*)d_in[15];
    const float* g0_bias = (const float*)d_in[16];
    const float* g1_Wl = (const float*)d_in[17];
    const float* g1_bl = (const float*)d_in[18];
    const float* g1_Wr = (const float*)d_in[19];
    const float* g1_br = (const float*)d_in[20];
    const float* g1_att = (const float*)d_in[21];
    const float* g1_bias = (const float*)d_in[22];
    const float* W_caps = (const float*)d_in[23];
    const float* F_w = (const float*)d_in[24];
    const float* F_b = (const float*)d_in[25];
    float* out = (float*)d_out;

    float *Xs,*Gi,*H0,*Emb,*hz,*P,*XN,*XL,*XR,*G0,*G1,*FUS,*PR;
    cudaGetSymbolAddress((void**)&Xs,  g_Xs);
    cudaGetSymbolAddress((void**)&Gi,  g_Gi);
    cudaGetSymbolAddress((void**)&H0,  g_H0);
    cudaGetSymbolAddress((void**)&Emb, g_Emb);
    cudaGetSymbolAddress((void**)&hz,  g_hz);
    cudaGetSymbolAddress((void**)&P,   g_P);
    cudaGetSymbolAddress((void**)&XN,  g_XN);
    cudaGetSymbolAddress((void**)&XL,  g_XL);
    cudaGetSymbolAddress((void**)&XR,  g_XR);
    cudaGetSymbolAddress((void**)&G0,  g_G0);
    cudaGetSymbolAddress((void**)&G1,  g_G1);
    cudaGetSymbolAddress((void**)&FUS, g_FUS);
    cudaGetSymbolAddress((void**)&PR,  g_PR);

    const int NTOT = Bc*Tc*Fc;
    k_zero<<<(Tc*Fc+255)/256, 256>>>(hz, Tc*Fc);
    k_sanitize<<<(NTOT+255)/256, 256>>>(inputs, Xs, NTOT);

    // layer 0
    k_sgemm<<<dim3(G3/128, (Bc*Tc)/128), 256>>>(Xs, Wih0, bih0, Gi, G3, Fc);
    for(int b=0;b<Bc;b++){
        const float* hp = b ? (H0 + (size_t)(b-1)*Tc*Fc) : hz;
        k_rgemm<<<dim3(G3/NTILE, KSPLIT), 256>>>(hp, Whh0, P);
        k_gate<<<64, 256>>>(b, P, Gi, bhh0, hp, H0);
    }
    // layer 1
    k_sgemm<<<dim3(G3/128, (Bc*Tc)/128), 256>>>(H0, Wih1, bih1, Gi, G3, Fc);
    for(int b=0;b<Bc;b++){
        const float* hp = b ? (Emb + (size_t)(b-1)*Tc*Fc) : hz;
        k_rgemm<<<dim3(G3/NTILE, KSPLIT), 256>>>(hp, Whh1, P);
        k_gate<<<64, 256>>>(b, P, Gi, bhh1, hp, Emb);
    }
    // attention -> node features
    k_attn<<<(Bc*Fc)/256, 256>>>(Emb, A_w, A_b, XN);
    // GAT layer 0
    k_lin64<<<Nn/64, 256>>>(XN, g0_Wl, g0_bl, g0_Wr, g0_br, XL, XR);
    k_gat<<<1024, 128>>>(XL, XR, g0_att, g0_bias, G0);
    // GAT layer 1
    k_lin64<<<Nn/64, 256>>>(G0, g1_Wl, g1_bl, g1_Wr, g1_br, XL, XR);
    k_gat<<<1024, 128>>>(XL, XR, g1_att, g1_bias, G1);
    // fusion + capsule priors
    k_fus<<<(Nn*128)/256, 256>>>(XN, G0, G1, FUS);
    k_sgemm<<<dim3(2048/128, Nn/128), 256>>>(FUS, W_caps, nullptr, PR, 2048, 128);
    // routing + head
    k_route<<<Bc, 64>>>(PR, F_w, F_b, out);
}